// round 2
// baseline (speedup 1.0000x reference)
#include <cuda_runtime.h>

#define LIN      15876      // (128-2)*(128-2)
#define LIN_PAD  15888      // next multiple of 16
#define TRI      8256       // 128*129/2
#define BATCH    64
#define NDIM     128
#define HW       128
#define OW       126

#define T_TILE   32
#define LC       16

// scratch (device globals — no allocation allowed)
__device__ float g_hT[LIN_PAD * BATCH];   // [l][b], rows >= LIN zeroed
__device__ float g_v[BATCH * TRI];        // [b][t]

// ---------------------------------------------------------------------------
// Kernel 1: fused conv1(3x3,1->4)+bias+relu -> conv2(1x1,4->1)+bias
// writes transposed activation hT[l][b] for the GEMM.
// ---------------------------------------------------------------------------
__global__ void conv_fuse_kernel(const float* __restrict__ x,
                                 const float* __restrict__ w1,
                                 const float* __restrict__ b1,
                                 const float* __restrict__ w2,
                                 const float* __restrict__ b2) {
    int idx = blockIdx.x * blockDim.x + threadIdx.x;
    if (idx >= BATCH * LIN_PAD) return;
    int b = idx / LIN_PAD;
    int l = idx - b * LIN_PAD;

    float val = 0.0f;
    if (l < LIN) {
        int i = l / OW;
        int j = l - i * OW;
        const float* xp = x + (size_t)b * (HW * HW) + i * HW + j;
        float acc = b2[0];
        #pragma unroll
        for (int c = 0; c < 4; c++) {
            float s = b1[c];
            #pragma unroll
            for (int di = 0; di < 3; di++) {
                #pragma unroll
                for (int dj = 0; dj < 3; dj++) {
                    s = fmaf(xp[di * HW + dj], w1[c * 9 + di * 3 + dj], s);
                }
            }
            acc = fmaf(w2[c], fmaxf(s, 0.0f), acc);
        }
        val = acc;
    }
    g_hT[l * BATCH + b] = val;   // zero for pad rows l in [LIN, LIN_PAD)
}

// ---------------------------------------------------------------------------
// Kernel 2: v[b][t] = sum_l hT[l][b] * W[t][l] + bias[t]
// 258 blocks x 256 threads. Block tile: 32 t-rows x 64 b. Per-thread 4t x 2b.
// ---------------------------------------------------------------------------
__global__ __launch_bounds__(256, 2)
void gemm_kernel(const float* __restrict__ W,
                 const float* __restrict__ bias) {
    __shared__ float Ws[T_TILE][LC];       // 32 x 16
    __shared__ float Hs[LC][BATCH];        // 16 x 64

    int tid = threadIdx.x;
    int tx  = tid & 31;      // -> b pair: b = 2*tx, 2*tx+1
    int ty  = tid >> 5;      // -> t group: t = t0 + 4*ty + i
    int t0  = blockIdx.x * T_TILE;

    float acc[4][2] = {{0.f, 0.f}, {0.f, 0.f}, {0.f, 0.f}, {0.f, 0.f}};

    for (int l0 = 0; l0 < LIN_PAD; l0 += LC) {
        // --- load H tile: 16x64 floats = 256 float4, one per thread ---
        {
            int row = tid >> 4;          // 0..15
            int c4  = tid & 15;          // 0..15 -> col = 4*c4
            float4 h4 = *reinterpret_cast<const float4*>(
                &g_hT[(size_t)(l0 + row) * BATCH + c4 * 4]);
            *reinterpret_cast<float4*>(&Hs[row][c4 * 4]) = h4;
        }
        // --- load W tile: 32x16 floats = 128 float4, threads 0..127 ---
        if (tid < 128) {
            int row = tid >> 2;          // 0..31
            int c4  = tid & 3;           // 0..3
            int l   = l0 + c4 * 4;
            float4 w4 = make_float4(0.f, 0.f, 0.f, 0.f);
            if (l < LIN) {               // LIN % 4 == 0, so full vec valid
                w4 = *reinterpret_cast<const float4*>(
                    &W[(size_t)(t0 + row) * LIN + l]);
            }
            *reinterpret_cast<float4*>(&Ws[row][c4 * 4]) = w4;
        }
        __syncthreads();

        #pragma unroll
        for (int lc = 0; lc < LC; lc++) {
            float2 h2 = *reinterpret_cast<const float2*>(&Hs[lc][tx * 2]);
            #pragma unroll
            for (int i = 0; i < 4; i++) {
                float wv = Ws[ty * 4 + i][lc];
                acc[i][0] = fmaf(wv, h2.x, acc[i][0]);
                acc[i][1] = fmaf(wv, h2.y, acc[i][1]);
            }
        }
        __syncthreads();
    }

    #pragma unroll
    for (int i = 0; i < 4; i++) {
        int t = t0 + ty * 4 + i;
        float bb = bias[t];
        g_v[(size_t)(tx * 2)     * TRI + t] = acc[i][0] + bb;
        g_v[(size_t)(tx * 2 + 1) * TRI + t] = acc[i][1] + bb;
    }
}

// ---------------------------------------------------------------------------
// Kernel 3: symmetric triu scatter: out[b,0,r,c] = v[b, t(min(r,c),max(r,c))]
// t(i,j) = i*N - i*(i-1)/2 + (j - i)   (np.triu_indices row-major order)
// ---------------------------------------------------------------------------
__global__ void scatter_kernel(float* __restrict__ out) {
    int idx = blockIdx.x * blockDim.x + threadIdx.x;
    if (idx >= BATCH * NDIM * NDIM) return;
    int b = idx >> 14;            // /16384
    int r = (idx >> 7) & 127;
    int c = idx & 127;
    int i = min(r, c);
    int j = max(r, c);
    int t = i * NDIM - (i * (i - 1)) / 2 + (j - i);
    out[idx] = g_v[(size_t)b * TRI + t];
}

// ---------------------------------------------------------------------------
extern "C" void kernel_launch(void* const* d_in, const int* in_sizes, int n_in,
                              void* d_out, int out_size) {
    const float* x       = (const float*)d_in[0];
    const float* conv1_w = (const float*)d_in[1];
    const float* conv1_b = (const float*)d_in[2];
    const float* conv2_w = (const float*)d_in[3];
    const float* conv2_b = (const float*)d_in[4];
    const float* out_w   = (const float*)d_in[5];
    const float* out_b   = (const float*)d_in[6];
    float* out = (float*)d_out;

    {
        int total = BATCH * LIN_PAD;
        conv_fuse_kernel<<<(total + 255) / 256, 256>>>(x, conv1_w, conv1_b,
                                                       conv2_w, conv2_b);
    }
    {
        gemm_kernel<<<TRI / T_TILE, 256>>>(out_w, out_b);   // 258 blocks
    }
    {
        int total = BATCH * NDIM * NDIM;
        scatter_kernel<<<(total + 255) / 256, 256>>>(out);
    }
}

// round 4
// speedup vs baseline: 4.1171x; 4.1171x over previous
#include <cuda_runtime.h>
#include <cuda_bf16.h>
#include <cstdint>

// ---------------------------------------------------------------------------
// Problem dims
// ---------------------------------------------------------------------------
#define HW        128
#define OW        126
#define LIN       15876              // (128-2)^2
#define K_TILE    64
#define N_KTILES  252                // LIN_PAD = 16128
#define LIN_PAD   (N_KTILES * K_TILE)
#define TRI       8256
#define BATCH     64
#define NDIM      128
#define T_PAD     8320               // 65*128
#define N_MTILES  65
#define KSPLIT    2
#define TILES_PER_SPLIT (N_KTILES / KSPLIT)   // 126 (even)

// SMEM layout (byte offsets). Row pitch 144B kills LDS bank conflicts.
#define A_PITCH   144
#define A_HI_OFF  0u
#define A_LO_OFF  18432u             // 128*144
#define B_STAGE   18432u             // hi(9216) + lo(9216)
#define B_OFF(s)  (36864u + (s) * B_STAGE)
#define SMEM_BYTES (36864 + 2 * 18432)   // 73728

// ---------------------------------------------------------------------------
// Scratch (device globals — no allocation allowed)
// ---------------------------------------------------------------------------
__device__ __nv_bfloat16 g_hb_hi[(size_t)BATCH * LIN_PAD];  // [b][l]
__device__ __nv_bfloat16 g_hb_lo[(size_t)BATCH * LIN_PAD];
__device__ float         g_vp[(size_t)KSPLIT * BATCH * T_PAD];

// ---------------------------------------------------------------------------
// helpers
// ---------------------------------------------------------------------------
__device__ __forceinline__ uint32_t smem_u32(const void* p) {
    uint32_t a;
    asm("{ .reg .u64 t; cvta.to.shared.u64 t, %1; cvt.u32.u64 %0, t; }"
        : "=r"(a) : "l"(p));
    return a;
}

__device__ __forceinline__ void cp_async16(uint32_t dst, const void* src) {
    asm volatile("cp.async.cg.shared.global [%0], [%1], 16;"
                 :: "r"(dst), "l"(src) : "memory");
}

__device__ __forceinline__ void mma_bf16(float& c0, float& c1, float& c2, float& c3,
                                         uint32_t a0, uint32_t a1, uint32_t a2, uint32_t a3,
                                         uint32_t b0, uint32_t b1) {
    asm volatile(
        "mma.sync.aligned.m16n8k16.row.col.f32.bf16.bf16.f32 "
        "{%0,%1,%2,%3}, {%4,%5,%6,%7}, {%8,%9}, {%0,%1,%2,%3};"
        : "+f"(c0), "+f"(c1), "+f"(c2), "+f"(c3)
        : "r"(a0), "r"(a1), "r"(a2), "r"(a3), "r"(b0), "r"(b1));
}

__device__ __forceinline__ uint32_t pack_bf16x2(float x, float y) {
    __nv_bfloat162 h = __floats2bfloat162_rn(x, y);
    return *reinterpret_cast<uint32_t*>(&h);
}

// ---------------------------------------------------------------------------
// Kernel 1: fused conv -> bf16 split h, plain [b][l] layout
// ---------------------------------------------------------------------------
__global__ void conv_fuse_kernel(const float* __restrict__ x,
                                 const float* __restrict__ w1,
                                 const float* __restrict__ b1,
                                 const float* __restrict__ w2,
                                 const float* __restrict__ b2) {
    int idx = blockIdx.x * blockDim.x + threadIdx.x;
    if (idx >= BATCH * LIN_PAD) return;
    int b = idx / LIN_PAD;
    int l = idx - b * LIN_PAD;

    float val = 0.0f;
    if (l < LIN) {
        int i = l / OW;
        int j = l - i * OW;
        const float* xp = x + (size_t)b * (HW * HW) + i * HW + j;
        float acc = b2[0];
        #pragma unroll
        for (int c = 0; c < 4; c++) {
            float s = b1[c];
            #pragma unroll
            for (int di = 0; di < 3; di++)
                #pragma unroll
                for (int dj = 0; dj < 3; dj++)
                    s = fmaf(xp[di * HW + dj], w1[c * 9 + di * 3 + dj], s);
            acc = fmaf(w2[c], fmaxf(s, 0.0f), acc);
        }
        val = acc;
    }
    __nv_bfloat16 hi = __float2bfloat16(val);
    __nv_bfloat16 lo = __float2bfloat16(val - __bfloat162float(hi));
    g_hb_hi[idx] = hi;
    g_hb_lo[idx] = lo;
}

// ---------------------------------------------------------------------------
// GEMM device helpers
// ---------------------------------------------------------------------------
__device__ __forceinline__ void ldg_a(const float* __restrict__ W,
                                      int t, int l0, int half, bool trow_ok,
                                      float4 (&a)[8]) {
    #pragma unroll
    for (int j = 0; j < 8; j++) {
        int l = l0 + (half * 8 + j) * 4;
        if (trow_ok && l < LIN)
            a[j] = *reinterpret_cast<const float4*>(W + (size_t)t * LIN + l);
        else
            a[j] = make_float4(0.f, 0.f, 0.f, 0.f);
    }
}

__device__ __forceinline__ void sts_a(char* smem, int row, int half,
                                      const float4 (&a)[8]) {
    #pragma unroll
    for (int j = 0; j < 8; j++) {
        int col4 = half * 8 + j;                 // float4 index within 64-col row
        uint32_t byt = (uint32_t)row * A_PITCH + (uint32_t)col4 * 8;
        uint32_t h0 = pack_bf16x2(a[j].x, a[j].y);
        uint32_t h1 = pack_bf16x2(a[j].z, a[j].w);
        float rx = a[j].x - __bfloat162float(__float2bfloat16(a[j].x));
        float ry = a[j].y - __bfloat162float(__float2bfloat16(a[j].y));
        float rz = a[j].z - __bfloat162float(__float2bfloat16(a[j].z));
        float rw = a[j].w - __bfloat162float(__float2bfloat16(a[j].w));
        uint32_t l0p = pack_bf16x2(rx, ry);
        uint32_t l1p = pack_bf16x2(rz, rw);
        *reinterpret_cast<uint2*>(smem + A_HI_OFF + byt) = make_uint2(h0, h1);
        *reinterpret_cast<uint2*>(smem + A_LO_OFF + byt) = make_uint2(l0p, l1p);
    }
}

__device__ __forceinline__ void cpasync_b(uint32_t sb, uint32_t stage_off,
                                          int ktg, int tid) {
    int l0 = ktg * K_TILE;
    #pragma unroll
    for (int i = 0; i < 2; i++) {
        int c = tid + 256 * i;                   // 0..511
        int row = c >> 3;                        // batch 0..63
        int ch  = c & 7;                         // 16B chunk
        uint32_t dst = sb + stage_off + (uint32_t)row * A_PITCH + (uint32_t)ch * 16;
        const __nv_bfloat16* srch = g_hb_hi + (size_t)row * LIN_PAD + l0 + ch * 8;
        const __nv_bfloat16* srcl = g_hb_lo + (size_t)row * LIN_PAD + l0 + ch * 8;
        cp_async16(dst, srch);
        cp_async16(dst + 9216u, srcl);
    }
}

__device__ __forceinline__ void compute_tile(char* smem, uint32_t b_off,
                                             int wm, int wn, int g, int t4,
                                             float (&acc)[2][4][4]) {
    #pragma unroll
    for (int ks = 0; ks < 4; ks++) {
        const int kk = ks * 16;
        uint32_t ah[2][4], al[2][4];
        #pragma unroll
        for (int mt = 0; mt < 2; mt++) {
            int r = wm * 32 + mt * 16 + g;
            uint32_t byt = (uint32_t)r * A_PITCH + (uint32_t)(kk * 2 + t4 * 4);
            ah[mt][0] = *reinterpret_cast<const uint32_t*>(smem + A_HI_OFF + byt);
            ah[mt][1] = *reinterpret_cast<const uint32_t*>(smem + A_HI_OFF + byt + 8 * A_PITCH);
            ah[mt][2] = *reinterpret_cast<const uint32_t*>(smem + A_HI_OFF + byt + 16);
            ah[mt][3] = *reinterpret_cast<const uint32_t*>(smem + A_HI_OFF + byt + 8 * A_PITCH + 16);
            al[mt][0] = *reinterpret_cast<const uint32_t*>(smem + A_LO_OFF + byt);
            al[mt][1] = *reinterpret_cast<const uint32_t*>(smem + A_LO_OFF + byt + 8 * A_PITCH);
            al[mt][2] = *reinterpret_cast<const uint32_t*>(smem + A_LO_OFF + byt + 16);
            al[mt][3] = *reinterpret_cast<const uint32_t*>(smem + A_LO_OFF + byt + 8 * A_PITCH + 16);
        }
        uint32_t bh[4][2], bl[4][2];
        #pragma unroll
        for (int nt = 0; nt < 4; nt++) {
            int n = wn * 32 + nt * 8 + g;
            uint32_t byt = (uint32_t)n * A_PITCH + (uint32_t)(kk * 2 + t4 * 4);
            bh[nt][0] = *reinterpret_cast<const uint32_t*>(smem + b_off + byt);
            bh[nt][1] = *reinterpret_cast<const uint32_t*>(smem + b_off + byt + 16);
            bl[nt][0] = *reinterpret_cast<const uint32_t*>(smem + b_off + 9216u + byt);
            bl[nt][1] = *reinterpret_cast<const uint32_t*>(smem + b_off + 9216u + byt + 16);
        }
        #pragma unroll
        for (int mt = 0; mt < 2; mt++)
            #pragma unroll
            for (int nt = 0; nt < 4; nt++) {
                float* c = acc[mt][nt];
                mma_bf16(c[0], c[1], c[2], c[3],
                         ah[mt][0], ah[mt][1], ah[mt][2], ah[mt][3],
                         bh[nt][0], bh[nt][1]);
                mma_bf16(c[0], c[1], c[2], c[3],
                         ah[mt][0], ah[mt][1], ah[mt][2], ah[mt][3],
                         bl[nt][0], bl[nt][1]);
                mma_bf16(c[0], c[1], c[2], c[3],
                         al[mt][0], al[mt][1], al[mt][2], al[mt][3],
                         bh[nt][0], bh[nt][1]);
            }
    }
}

// ---------------------------------------------------------------------------
// Kernel 2: bf16-split HMMA GEMM, split-K x2 -> 130 CTAs x 256 threads
// D[t0+0..127][b 0..63] = sum_l W[t][l] * h[l][b]
// ---------------------------------------------------------------------------
__global__ __launch_bounds__(256, 1)
void gemm_tc_kernel(const float* __restrict__ W) {
    extern __shared__ char smem[];
    const uint32_t sb = smem_u32(smem);

    const int tid = threadIdx.x;
    const int wid = tid >> 5;
    const int lid = tid & 31;
    const int g   = lid >> 2;       // mma group id
    const int t4  = lid & 3;        // thread-in-group
    const int wm  = wid & 3;        // warp row (4 x 32 rows)
    const int wn  = wid >> 2;       // warp col (2 x 32 cols)

    const int mtile = blockIdx.x >> 1;
    const int split = blockIdx.x & 1;
    const int t0    = mtile * 128;
    const int kt0   = split * TILES_PER_SPLIT;

    // A LDG mapping: thread -> fixed row, half
    const int arow  = tid >> 1;
    const int ahalf = tid & 1;
    const int atrow = t0 + arow;
    const bool trow_ok = (atrow < TRI);

    float acc[2][4][4];
    #pragma unroll
    for (int i = 0; i < 2; i++)
        #pragma unroll
        for (int j = 0; j < 4; j++)
            #pragma unroll
            for (int k = 0; k < 4; k++)
                acc[i][j][k] = 0.f;

    float4 aE[8], aO[8];

    // prologue: tile 0
    cpasync_b(sb, B_OFF(0), kt0 + 0, tid);
    asm volatile("cp.async.commit_group;" ::: "memory");
    ldg_a(W, atrow, (kt0 + 0) * K_TILE, ahalf, trow_ok, aE);

    for (int kt = 0; kt < TILES_PER_SPLIT; kt += 2) {
        // ---- even tile kt ----
        {
            bool more = (kt + 1 < TILES_PER_SPLIT);
            if (more) {
                cpasync_b(sb, B_OFF(1), kt0 + kt + 1, tid);
                asm volatile("cp.async.commit_group;" ::: "memory");
                ldg_a(W, atrow, (kt0 + kt + 1) * K_TILE, ahalf, trow_ok, aO);
                asm volatile("cp.async.wait_group 1;" ::: "memory");
            } else {
                asm volatile("cp.async.wait_group 0;" ::: "memory");
            }
            sts_a(smem, arow, ahalf, aE);
            __syncthreads();
            compute_tile(smem, B_OFF(0), wm, wn, g, t4, acc);
            __syncthreads();
        }
        // ---- odd tile kt+1 ----
        if (kt + 1 < TILES_PER_SPLIT) {
            bool more = (kt + 2 < TILES_PER_SPLIT);
            if (more) {
                cpasync_b(sb, B_OFF(0), kt0 + kt + 2, tid);
                asm volatile("cp.async.commit_group;" ::: "memory");
                ldg_a(W, atrow, (kt0 + kt + 2) * K_TILE, ahalf, trow_ok, aE);
                asm volatile("cp.async.wait_group 1;" ::: "memory");
            } else {
                asm volatile("cp.async.wait_group 0;" ::: "memory");
            }
            sts_a(smem, arow, ahalf, aO);
            __syncthreads();
            compute_tile(smem, B_OFF(1), wm, wn, g, t4, acc);
            __syncthreads();
        }
    }

    // ---- epilogue: write partials to g_vp[split*64 + b][t] ----
    float* vp = g_vp + (size_t)split * BATCH * T_PAD;
    #pragma unroll
    for (int mt = 0; mt < 2; mt++) {
        #pragma unroll
        for (int nt = 0; nt < 4; nt++) {
            int r0 = t0 + wm * 32 + mt * 16 + g;
            int cb = wn * 32 + nt * 8 + 2 * t4;
            vp[(size_t)cb       * T_PAD + r0]     = acc[mt][nt][0];
            vp[(size_t)(cb + 1) * T_PAD + r0]     = acc[mt][nt][1];
            vp[(size_t)cb       * T_PAD + r0 + 8] = acc[mt][nt][2];
            vp[(size_t)(cb + 1) * T_PAD + r0 + 8] = acc[mt][nt][3];
        }
    }
}

// ---------------------------------------------------------------------------
// Kernel 3: symmetric triu scatter + split-K reduce + bias
// ---------------------------------------------------------------------------
__global__ void scatter_kernel(float* __restrict__ out,
                               const float* __restrict__ bias) {
    int idx = blockIdx.x * blockDim.x + threadIdx.x;
    if (idx >= BATCH * NDIM * NDIM) return;
    int b = idx >> 14;
    int r = (idx >> 7) & 127;
    int c = idx & 127;
    int i = min(r, c);
    int j = max(r, c);
    int t = i * NDIM - (i * (i - 1)) / 2 + (j - i);
    out[idx] = g_vp[(size_t)b * T_PAD + t] +
               g_vp[(size_t)(BATCH + b) * T_PAD + t] + bias[t];
}

// ---------------------------------------------------------------------------
extern "C" void kernel_launch(void* const* d_in, const int* in_sizes, int n_in,
                              void* d_out, int out_size) {
    const float* x       = (const float*)d_in[0];
    const float* conv1_w = (const float*)d_in[1];
    const float* conv1_b = (const float*)d_in[2];
    const float* conv2_w = (const float*)d_in[3];
    const float* conv2_b = (const float*)d_in[4];
    const float* out_w   = (const float*)d_in[5];
    const float* out_b   = (const float*)d_in[6];
    float* out = (float*)d_out;

    cudaFuncSetAttribute(gemm_tc_kernel,
                         cudaFuncAttributeMaxDynamicSharedMemorySize, SMEM_BYTES);

    {
        int total = BATCH * LIN_PAD;
        conv_fuse_kernel<<<(total + 255) / 256, 256>>>(x, conv1_w, conv1_b,
                                                       conv2_w, conv2_b);
    }
    gemm_tc_kernel<<<N_MTILES * KSPLIT, 256, SMEM_BYTES>>>(out_w);
    {
        int total = BATCH * NDIM * NDIM;
        scatter_kernel<<<(total + 255) / 256, 256>>>(out, out_b);
    }
}

// round 5
// speedup vs baseline: 4.3996x; 1.0686x over previous
#include <cuda_runtime.h>
#include <cuda_bf16.h>
#include <cstdint>

// ---------------------------------------------------------------------------
// Problem dims
// ---------------------------------------------------------------------------
#define HW        128
#define OW        126
#define LIN       15876              // (128-2)^2
#define K_TILE    64
#define N_KTILES  252                // LIN_PAD = 16128
#define LIN_PAD   (N_KTILES * K_TILE)
#define TRI       8256
#define BATCH     64
#define NDIM      128
#define T_PAD     8320               // 65*128
#define N_MTILES  65
#define KSPLIT    2
#define TILES_PER_SPLIT (N_KTILES / KSPLIT)   // 126 (even)

// SMEM layout. Row pitch 144B -> conflict-free LDS/ldmatrix.
#define A_PITCH   144
#define A_HI_OFF  0u
#define A_LO_OFF  18432u             // 128*144
#define B_STAGE   18432u             // hi(9216) + lo(9216)
#define B_OFF(s)  (36864u + (s) * B_STAGE)
#define SMEM_BYTES (36864 + 2 * 18432)   // 73728

// ---------------------------------------------------------------------------
// Scratch (device globals — no allocation allowed)
// ---------------------------------------------------------------------------
__device__ __nv_bfloat16 g_hb_hi[(size_t)BATCH * LIN_PAD];  // [b][l]
__device__ __nv_bfloat16 g_hb_lo[(size_t)BATCH * LIN_PAD];
__device__ float         g_vp[(size_t)KSPLIT * BATCH * T_PAD];

// ---------------------------------------------------------------------------
// helpers
// ---------------------------------------------------------------------------
__device__ __forceinline__ uint32_t smem_u32(const void* p) {
    uint32_t a;
    asm("{ .reg .u64 t; cvta.to.shared.u64 t, %1; cvt.u32.u64 %0, t; }"
        : "=r"(a) : "l"(p));
    return a;
}

__device__ __forceinline__ void cp_async16(uint32_t dst, const void* src) {
    asm volatile("cp.async.cg.shared.global [%0], [%1], 16;"
                 :: "r"(dst), "l"(src) : "memory");
}

__device__ __forceinline__ void ldsm4(uint32_t& r0, uint32_t& r1,
                                      uint32_t& r2, uint32_t& r3, uint32_t addr) {
    asm volatile("ldmatrix.sync.aligned.m8n8.x4.shared.b16 {%0,%1,%2,%3}, [%4];"
                 : "=r"(r0), "=r"(r1), "=r"(r2), "=r"(r3) : "r"(addr));
}

__device__ __forceinline__ void mma_bf16(float* c,
                                         uint32_t a0, uint32_t a1, uint32_t a2, uint32_t a3,
                                         uint32_t b0, uint32_t b1) {
    asm volatile(
        "mma.sync.aligned.m16n8k16.row.col.f32.bf16.bf16.f32 "
        "{%0,%1,%2,%3}, {%4,%5,%6,%7}, {%8,%9}, {%0,%1,%2,%3};"
        : "+f"(c[0]), "+f"(c[1]), "+f"(c[2]), "+f"(c[3])
        : "r"(a0), "r"(a1), "r"(a2), "r"(a3), "r"(b0), "r"(b1));
}

__device__ __forceinline__ uint32_t cvt_bf16x2(float x, float y) {
    __nv_bfloat162 h = __floats2bfloat162_rn(x, y);
    return *reinterpret_cast<uint32_t*>(&h);
}

// ---------------------------------------------------------------------------
// Kernel 1: fused conv -> bf16 split h, plain [b][l] layout
// ---------------------------------------------------------------------------
__global__ void conv_fuse_kernel(const float* __restrict__ x,
                                 const float* __restrict__ w1,
                                 const float* __restrict__ b1,
                                 const float* __restrict__ w2,
                                 const float* __restrict__ b2) {
    int idx = blockIdx.x * blockDim.x + threadIdx.x;
    if (idx >= BATCH * LIN_PAD) return;
    int b = idx / LIN_PAD;
    int l = idx - b * LIN_PAD;

    float val = 0.0f;
    if (l < LIN) {
        int i = l / OW;
        int j = l - i * OW;
        const float* xp = x + (size_t)b * (HW * HW) + i * HW + j;
        float acc = b2[0];
        #pragma unroll
        for (int c = 0; c < 4; c++) {
            float s = b1[c];
            #pragma unroll
            for (int di = 0; di < 3; di++)
                #pragma unroll
                for (int dj = 0; dj < 3; dj++)
                    s = fmaf(xp[di * HW + dj], w1[c * 9 + di * 3 + dj], s);
            acc = fmaf(w2[c], fmaxf(s, 0.0f), acc);
        }
        val = acc;
    }
    __nv_bfloat16 hi = __float2bfloat16(val);
    __nv_bfloat16 lo = __float2bfloat16(val - __bfloat162float(hi));
    g_hb_hi[idx] = hi;
    g_hb_lo[idx] = lo;
}

// ---------------------------------------------------------------------------
// GEMM device helpers (512 threads: arow = tid>>2, aq = tid&3)
// ---------------------------------------------------------------------------
__device__ __forceinline__ void ldg_a(const float* __restrict__ W,
                                      int t, int l0, int aq, bool trow_ok,
                                      float4 (&a)[4]) {
    #pragma unroll
    for (int j = 0; j < 4; j++) {
        int l = l0 + (aq * 4 + j) * 4;
        if (trow_ok && l < LIN)
            a[j] = *reinterpret_cast<const float4*>(W + (size_t)t * LIN + l);
        else
            a[j] = make_float4(0.f, 0.f, 0.f, 0.f);
    }
}

__device__ __forceinline__ void sts_a(char* smem, int row, int aq,
                                      const float4 (&a)[4]) {
    #pragma unroll
    for (int j = 0; j < 4; j++) {
        uint32_t byt = (uint32_t)row * A_PITCH + (uint32_t)(aq * 4 + j) * 8;
        uint32_t h0 = cvt_bf16x2(a[j].x, a[j].y);
        uint32_t h1 = cvt_bf16x2(a[j].z, a[j].w);
        // unpack hi back to fp32 (bf16 == top 16 bits of fp32)
        float hx = __uint_as_float(h0 << 16);
        float hy = __uint_as_float(h0 & 0xFFFF0000u);
        float hz = __uint_as_float(h1 << 16);
        float hw = __uint_as_float(h1 & 0xFFFF0000u);
        uint32_t l0p = cvt_bf16x2(a[j].x - hx, a[j].y - hy);
        uint32_t l1p = cvt_bf16x2(a[j].z - hz, a[j].w - hw);
        *reinterpret_cast<uint2*>(smem + A_HI_OFF + byt) = make_uint2(h0, h1);
        *reinterpret_cast<uint2*>(smem + A_LO_OFF + byt) = make_uint2(l0p, l1p);
    }
}

__device__ __forceinline__ void cpasync_b(uint32_t sb, uint32_t stage_off,
                                          int ktg, int tid) {
    int l0 = ktg * K_TILE;
    int row = tid >> 3;                          // batch 0..63
    int ch  = tid & 7;                           // 16B chunk
    uint32_t dst = sb + stage_off + (uint32_t)row * A_PITCH + (uint32_t)ch * 16;
    cp_async16(dst,         g_hb_hi + (size_t)row * LIN_PAD + l0 + ch * 8);
    cp_async16(dst + 9216u, g_hb_lo + (size_t)row * LIN_PAD + l0 + ch * 8);
}

// warp tile: 32 rows (wm) x 16 cols (wn); frags via ldmatrix.x4
__device__ __forceinline__ void compute_tile(uint32_t sb, uint32_t b_off,
                                             int wm, int wn, int lid,
                                             float (&acc)[2][2][4]) {
    const uint32_t lrow = (uint32_t)(lid & 15);
    const uint32_t lhi  = (uint32_t)((lid >> 4) << 4);

    uint32_t aH0 = sb + A_HI_OFF + (wm * 32 + lrow) * A_PITCH + lhi;
    uint32_t aH1 = aH0 + 16 * A_PITCH;
    uint32_t aL0 = aH0 + (A_LO_OFF - A_HI_OFF);
    uint32_t aL1 = aH1 + (A_LO_OFF - A_HI_OFF);
    uint32_t bH  = sb + b_off + (wn * 16 + lrow) * A_PITCH + lhi;
    uint32_t bL  = bH + 9216u;

    #pragma unroll
    for (int ks = 0; ks < 4; ks++) {
        const uint32_t ko = (uint32_t)ks * 32;   // 16 bf16 = 32 B per kstep

        uint32_t ah[2][4], al[2][4];
        ldsm4(ah[0][0], ah[0][1], ah[0][2], ah[0][3], aH0 + ko);
        ldsm4(ah[1][0], ah[1][1], ah[1][2], ah[1][3], aH1 + ko);
        ldsm4(al[0][0], al[0][1], al[0][2], al[0][3], aL0 + ko);
        ldsm4(al[1][0], al[1][1], al[1][2], al[1][3], aL1 + ko);

        uint32_t b0, b1, b2, b3, c0, c1, c2, c3;
        ldsm4(b0, b1, b2, b3, bH + ko);          // hi: frag0 n0-7, frag1 n8-15
        ldsm4(c0, c1, c2, c3, bL + ko);          // lo
        uint32_t bh[2][2] = {{b0, b2}, {b1, b3}};
        uint32_t bl[2][2] = {{c0, c2}, {c1, c3}};

        #pragma unroll
        for (int mt = 0; mt < 2; mt++)
            #pragma unroll
            for (int nt = 0; nt < 2; nt++) {
                mma_bf16(acc[mt][nt], ah[mt][0], ah[mt][1], ah[mt][2], ah[mt][3],
                         bh[nt][0], bh[nt][1]);
                mma_bf16(acc[mt][nt], ah[mt][0], ah[mt][1], ah[mt][2], ah[mt][3],
                         bl[nt][0], bl[nt][1]);
                mma_bf16(acc[mt][nt], al[mt][0], al[mt][1], al[mt][2], al[mt][3],
                         bh[nt][0], bh[nt][1]);
            }
    }
}

// ---------------------------------------------------------------------------
// Kernel 2: bf16-split HMMA GEMM, 130 CTAs x 512 threads (16 warps)
// ---------------------------------------------------------------------------
__global__ __launch_bounds__(512, 1)
void gemm_tc_kernel(const float* __restrict__ W) {
    extern __shared__ char smem[];
    const uint32_t sb = smem_u32(smem);

    const int tid = threadIdx.x;
    const int wid = tid >> 5;
    const int lid = tid & 31;
    const int g   = lid >> 2;
    const int t4  = lid & 3;
    const int wm  = wid & 3;        // 4 row groups x 32
    const int wn  = wid >> 2;       // 4 col groups x 16

    const int mtile = blockIdx.x >> 1;
    const int split = blockIdx.x & 1;
    const int t0    = mtile * 128;
    const int kt0   = split * TILES_PER_SPLIT;

    const int arow  = tid >> 2;
    const int aq    = tid & 3;
    const int atrow = t0 + arow;
    const bool trow_ok = (atrow < TRI);

    float acc[2][2][4];
    #pragma unroll
    for (int i = 0; i < 2; i++)
        #pragma unroll
        for (int j = 0; j < 2; j++)
            #pragma unroll
            for (int k = 0; k < 4; k++)
                acc[i][j][k] = 0.f;

    float4 aE[4], aO[4];

    cpasync_b(sb, B_OFF(0), kt0 + 0, tid);
    asm volatile("cp.async.commit_group;" ::: "memory");
    ldg_a(W, atrow, (kt0 + 0) * K_TILE, aq, trow_ok, aE);

    for (int kt = 0; kt < TILES_PER_SPLIT; kt += 2) {
        // ---- even tile kt ----
        {
            bool more = (kt + 1 < TILES_PER_SPLIT);
            if (more) {
                cpasync_b(sb, B_OFF(1), kt0 + kt + 1, tid);
                asm volatile("cp.async.commit_group;" ::: "memory");
                ldg_a(W, atrow, (kt0 + kt + 1) * K_TILE, aq, trow_ok, aO);
                asm volatile("cp.async.wait_group 1;" ::: "memory");
            } else {
                asm volatile("cp.async.wait_group 0;" ::: "memory");
            }
            sts_a(smem, arow, aq, aE);
            __syncthreads();
            compute_tile(sb, B_OFF(0), wm, wn, lid, acc);
            __syncthreads();
        }
        // ---- odd tile kt+1 ----
        if (kt + 1 < TILES_PER_SPLIT) {
            bool more = (kt + 2 < TILES_PER_SPLIT);
            if (more) {
                cpasync_b(sb, B_OFF(0), kt0 + kt + 2, tid);
                asm volatile("cp.async.commit_group;" ::: "memory");
                ldg_a(W, atrow, (kt0 + kt + 2) * K_TILE, aq, trow_ok, aE);
                asm volatile("cp.async.wait_group 1;" ::: "memory");
            } else {
                asm volatile("cp.async.wait_group 0;" ::: "memory");
            }
            sts_a(smem, arow, aq, aO);
            __syncthreads();
            compute_tile(sb, B_OFF(1), wm, wn, lid, acc);
            __syncthreads();
        }
    }

    // ---- epilogue ----
    float* vp = g_vp + (size_t)split * BATCH * T_PAD;
    #pragma unroll
    for (int mt = 0; mt < 2; mt++) {
        #pragma unroll
        for (int nt = 0; nt < 2; nt++) {
            int r  = t0 + wm * 32 + mt * 16 + g;
            int cb = wn * 16 + nt * 8 + 2 * t4;
            vp[(size_t)cb       * T_PAD + r]     = acc[mt][nt][0];
            vp[(size_t)(cb + 1) * T_PAD + r]     = acc[mt][nt][1];
            vp[(size_t)cb       * T_PAD + r + 8] = acc[mt][nt][2];
            vp[(size_t)(cb + 1) * T_PAD + r + 8] = acc[mt][nt][3];
        }
    }
}

// ---------------------------------------------------------------------------
// Kernel 3: symmetric triu scatter + split-K reduce + bias
// ---------------------------------------------------------------------------
__global__ void scatter_kernel(float* __restrict__ out,
                               const float* __restrict__ bias) {
    int idx = blockIdx.x * blockDim.x + threadIdx.x;
    if (idx >= BATCH * NDIM * NDIM) return;
    int b = idx >> 14;
    int r = (idx >> 7) & 127;
    int c = idx & 127;
    int i = min(r, c);
    int j = max(r, c);
    int t = i * NDIM - (i * (i - 1)) / 2 + (j - i);
    out[idx] = g_vp[(size_t)b * T_PAD + t] +
               g_vp[(size_t)(BATCH + b) * T_PAD + t] + bias[t];
}

// ---------------------------------------------------------------------------
extern "C" void kernel_launch(void* const* d_in, const int* in_sizes, int n_in,
                              void* d_out, int out_size) {
    const float* x       = (const float*)d_in[0];
    const float* conv1_w = (const float*)d_in[1];
    const float* conv1_b = (const float*)d_in[2];
    const float* conv2_w = (const float*)d_in[3];
    const float* conv2_b = (const float*)d_in[4];
    const float* out_w   = (const float*)d_in[5];
    const float* out_b   = (const float*)d_in[6];
    float* out = (float*)d_out;

    cudaFuncSetAttribute(gemm_tc_kernel,
                         cudaFuncAttributeMaxDynamicSharedMemorySize, SMEM_BYTES);

    {
        int total = BATCH * LIN_PAD;
        conv_fuse_kernel<<<(total + 255) / 256, 256>>>(x, conv1_w, conv1_b,
                                                       conv2_w, conv2_b);
    }
    gemm_tc_kernel<<<N_MTILES * KSPLIT, 512, SMEM_BYTES>>>(out_w);
    {
        int total = BATCH * NDIM * NDIM;
        scatter_kernel<<<(total + 255) / 256, 256>>>(out, out_b);
    }
}

// round 6
// speedup vs baseline: 5.1370x; 1.1676x over previous
#include <cuda_runtime.h>
#include <cuda_bf16.h>
#include <cstdint>

// ---------------------------------------------------------------------------
// Problem dims
// ---------------------------------------------------------------------------
#define HW        128
#define OW        126
#define LIN       15876              // (128-2)^2
#define K_TILE    64
#define N_KTILES  252                // LIN_PAD = 16128
#define LIN_PAD   (N_KTILES * K_TILE)
#define TRI       8256
#define BATCH     64
#define NDIM      128
#define T_PAD     8320               // 65*128
#define N_MTILES  65
#define KSPLIT    2
#define TILES_PER_SPLIT (N_KTILES / KSPLIT)   // 126

// SMEM layout. Row pitch 144B -> conflict-free ldmatrix.
// A: 2 stages of (hi 18432 + lo 18432) = 2 x 36864
// B: 3 stages of (hi 9216 + lo 9216)  = 3 x 18432
#define A_PITCH   144
#define A_STAGE_SZ 36864u
#define A_LO_REL  18432u
#define A_OFF(s)  ((uint32_t)(s) * A_STAGE_SZ)
#define B_BASE    73728u
#define B_STAGE_SZ 18432u
#define B_OFF(s)  (B_BASE + (uint32_t)(s) * B_STAGE_SZ)
#define SMEM_BYTES (73728 + 3 * 18432)      // 129024

// ---------------------------------------------------------------------------
// Scratch (device globals — no allocation allowed)
// ---------------------------------------------------------------------------
__device__ __nv_bfloat16 g_hb_hi[(size_t)BATCH * LIN_PAD];  // [b][l]
__device__ __nv_bfloat16 g_hb_lo[(size_t)BATCH * LIN_PAD];
__device__ float         g_vp[(size_t)KSPLIT * BATCH * T_PAD];

// ---------------------------------------------------------------------------
// helpers
// ---------------------------------------------------------------------------
__device__ __forceinline__ uint32_t smem_u32(const void* p) {
    uint32_t a;
    asm("{ .reg .u64 t; cvta.to.shared.u64 t, %1; cvt.u32.u64 %0, t; }"
        : "=r"(a) : "l"(p));
    return a;
}

__device__ __forceinline__ void cp_async16(uint32_t dst, const void* src) {
    asm volatile("cp.async.cg.shared.global [%0], [%1], 16;"
                 :: "r"(dst), "l"(src) : "memory");
}
__device__ __forceinline__ void cp_commit() {
    asm volatile("cp.async.commit_group;" ::: "memory");
}
template <int N>
__device__ __forceinline__ void cp_wait() {
    asm volatile("cp.async.wait_group %0;" :: "n"(N) : "memory");
}

__device__ __forceinline__ void ldsm4(uint32_t& r0, uint32_t& r1,
                                      uint32_t& r2, uint32_t& r3, uint32_t addr) {
    asm volatile("ldmatrix.sync.aligned.m8n8.x4.shared.b16 {%0,%1,%2,%3}, [%4];"
                 : "=r"(r0), "=r"(r1), "=r"(r2), "=r"(r3) : "r"(addr));
}

__device__ __forceinline__ void mma_bf16(float* c,
                                         uint32_t a0, uint32_t a1, uint32_t a2, uint32_t a3,
                                         uint32_t b0, uint32_t b1) {
    asm volatile(
        "mma.sync.aligned.m16n8k16.row.col.f32.bf16.bf16.f32 "
        "{%0,%1,%2,%3}, {%4,%5,%6,%7}, {%8,%9}, {%0,%1,%2,%3};"
        : "+f"(c[0]), "+f"(c[1]), "+f"(c[2]), "+f"(c[3])
        : "r"(a0), "r"(a1), "r"(a2), "r"(a3), "r"(b0), "r"(b1));
}

__device__ __forceinline__ uint32_t cvt_bf16x2(float x, float y) {
    __nv_bfloat162 h = __floats2bfloat162_rn(x, y);
    return *reinterpret_cast<uint32_t*>(&h);
}

// ---------------------------------------------------------------------------
// Kernel 1: fused conv -> bf16 split h, plain [b][l] layout
// ---------------------------------------------------------------------------
__global__ void conv_fuse_kernel(const float* __restrict__ x,
                                 const float* __restrict__ w1,
                                 const float* __restrict__ b1,
                                 const float* __restrict__ w2,
                                 const float* __restrict__ b2) {
    int idx = blockIdx.x * blockDim.x + threadIdx.x;
    if (idx >= BATCH * LIN_PAD) return;
    int b = idx / LIN_PAD;
    int l = idx - b * LIN_PAD;

    float val = 0.0f;
    if (l < LIN) {
        int i = l / OW;
        int j = l - i * OW;
        const float* xp = x + (size_t)b * (HW * HW) + i * HW + j;
        float acc = b2[0];
        #pragma unroll
        for (int c = 0; c < 4; c++) {
            float s = b1[c];
            #pragma unroll
            for (int di = 0; di < 3; di++)
                #pragma unroll
                for (int dj = 0; dj < 3; dj++)
                    s = fmaf(xp[di * HW + dj], w1[c * 9 + di * 3 + dj], s);
            acc = fmaf(w2[c], fmaxf(s, 0.0f), acc);
        }
        val = acc;
    }
    __nv_bfloat16 hi = __float2bfloat16(val);
    __nv_bfloat16 lo = __float2bfloat16(val - __bfloat162float(hi));
    g_hb_hi[idx] = hi;
    g_hb_lo[idx] = lo;
}

// ---------------------------------------------------------------------------
// GEMM device helpers (512 threads: arow = tid>>2, aq = tid&3)
// ---------------------------------------------------------------------------
__device__ __forceinline__ void ldg_a(const float* __restrict__ W,
                                      int t, int l0, int aq, bool trow_ok,
                                      float4 (&a)[4]) {
    #pragma unroll
    for (int j = 0; j < 4; j++) {
        int l = l0 + (aq * 4 + j) * 4;
        if (trow_ok && l < LIN)
            a[j] = *reinterpret_cast<const float4*>(W + (size_t)t * LIN + l);
        else
            a[j] = make_float4(0.f, 0.f, 0.f, 0.f);
    }
}

__device__ __forceinline__ void sts_a(char* smem, uint32_t a_off, int row, int aq,
                                      const float4 (&a)[4]) {
    #pragma unroll
    for (int j = 0; j < 4; j++) {
        uint32_t byt = a_off + (uint32_t)row * A_PITCH + (uint32_t)(aq * 4 + j) * 8;
        uint32_t h0 = cvt_bf16x2(a[j].x, a[j].y);
        uint32_t h1 = cvt_bf16x2(a[j].z, a[j].w);
        float hx = __uint_as_float(h0 << 16);
        float hy = __uint_as_float(h0 & 0xFFFF0000u);
        float hz = __uint_as_float(h1 << 16);
        float hw = __uint_as_float(h1 & 0xFFFF0000u);
        uint32_t l0p = cvt_bf16x2(a[j].x - hx, a[j].y - hy);
        uint32_t l1p = cvt_bf16x2(a[j].z - hz, a[j].w - hw);
        *reinterpret_cast<uint2*>(smem + byt)            = make_uint2(h0, h1);
        *reinterpret_cast<uint2*>(smem + byt + A_LO_REL) = make_uint2(l0p, l1p);
    }
}

__device__ __forceinline__ void cpasync_b(uint32_t sb, uint32_t stage_off,
                                          int ktg, int tid) {
    int l0 = ktg * K_TILE;
    int row = tid >> 3;                          // batch 0..63
    int ch  = tid & 7;                           // 16B chunk
    uint32_t dst = sb + stage_off + (uint32_t)row * A_PITCH + (uint32_t)ch * 16;
    cp_async16(dst,         g_hb_hi + (size_t)row * LIN_PAD + l0 + ch * 8);
    cp_async16(dst + 9216u, g_hb_lo + (size_t)row * LIN_PAD + l0 + ch * 8);
}

// warp tile: 32 rows (wm) x 16 cols (wn); frags via ldmatrix.x4
__device__ __forceinline__ void compute_tile(uint32_t sb, uint32_t a_off,
                                             uint32_t b_off,
                                             int wm, int wn, int lid,
                                             float (&acc)[2][2][4]) {
    const uint32_t lrow = (uint32_t)(lid & 15);
    const uint32_t lhi  = (uint32_t)((lid >> 4) << 4);

    uint32_t aH0 = sb + a_off + (wm * 32 + lrow) * A_PITCH + lhi;
    uint32_t aH1 = aH0 + 16 * A_PITCH;
    uint32_t aL0 = aH0 + A_LO_REL;
    uint32_t aL1 = aH1 + A_LO_REL;
    uint32_t bH  = sb + b_off + (wn * 16 + lrow) * A_PITCH + lhi;
    uint32_t bL  = bH + 9216u;

    #pragma unroll
    for (int ks = 0; ks < 4; ks++) {
        const uint32_t ko = (uint32_t)ks * 32;   // 16 bf16 = 32 B per kstep

        uint32_t ah[2][4], al[2][4];
        ldsm4(ah[0][0], ah[0][1], ah[0][2], ah[0][3], aH0 + ko);
        ldsm4(ah[1][0], ah[1][1], ah[1][2], ah[1][3], aH1 + ko);
        ldsm4(al[0][0], al[0][1], al[0][2], al[0][3], aL0 + ko);
        ldsm4(al[1][0], al[1][1], al[1][2], al[1][3], aL1 + ko);

        uint32_t b0, b1, b2, b3, c0, c1, c2, c3;
        ldsm4(b0, b1, b2, b3, bH + ko);
        ldsm4(c0, c1, c2, c3, bL + ko);
        uint32_t bh[2][2] = {{b0, b2}, {b1, b3}};
        uint32_t bl[2][2] = {{c0, c2}, {c1, c3}};

        #pragma unroll
        for (int mt = 0; mt < 2; mt++)
            #pragma unroll
            for (int nt = 0; nt < 2; nt++) {
                mma_bf16(acc[mt][nt], ah[mt][0], ah[mt][1], ah[mt][2], ah[mt][3],
                         bh[nt][0], bh[nt][1]);
                mma_bf16(acc[mt][nt], ah[mt][0], ah[mt][1], ah[mt][2], ah[mt][3],
                         bl[nt][0], bl[nt][1]);
                mma_bf16(acc[mt][nt], al[mt][0], al[mt][1], al[mt][2], al[mt][3],
                         bh[nt][0], bh[nt][1]);
            }
    }
}

// ---------------------------------------------------------------------------
// Kernel 2: bf16-split HMMA GEMM, 130 CTAs x 512 threads (16 warps)
// A double-buffered, B triple-buffered, ONE barrier per tile.
// ---------------------------------------------------------------------------
__global__ __launch_bounds__(512, 1)
void gemm_tc_kernel(const float* __restrict__ W) {
    extern __shared__ char smem[];
    const uint32_t sb = smem_u32(smem);

    const int tid = threadIdx.x;
    const int wid = tid >> 5;
    const int lid = tid & 31;
    const int g   = lid >> 2;
    const int t4  = lid & 3;
    const int wm  = wid & 3;        // 4 row groups x 32
    const int wn  = wid >> 2;       // 4 col groups x 16

    const int mtile = blockIdx.x >> 1;
    const int split = blockIdx.x & 1;
    const int t0    = mtile * 128;
    const int kt0   = split * TILES_PER_SPLIT;

    const int arow  = tid >> 2;
    const int aq    = tid & 3;
    const int atrow = t0 + arow;
    const bool trow_ok = (atrow < TRI);

    float acc[2][2][4];
    #pragma unroll
    for (int i = 0; i < 2; i++)
        #pragma unroll
        for (int j = 0; j < 2; j++)
            #pragma unroll
            for (int k = 0; k < 4; k++)
                acc[i][j][k] = 0.f;

    float4 aR[4];

    // ---- prologue: B tiles 0,1 in flight; A tile 0 in smem; aR holds tile 1
    cpasync_b(sb, B_OFF(0), kt0 + 0, tid);
    cp_commit();
    cpasync_b(sb, B_OFF(1), kt0 + 1, tid);
    cp_commit();
    ldg_a(W, atrow, (kt0 + 0) * K_TILE, aq, trow_ok, aR);
    sts_a(smem, A_OFF(0), arow, aq, aR);
    ldg_a(W, atrow, (kt0 + 1) * K_TILE, aq, trow_ok, aR);
    cp_wait<1>();        // B(0) complete
    __syncthreads();     // A(0) visible

    int bs = 0;          // B stage of current tile
    for (int kt = 0; kt < TILES_PER_SPLIT; kt++) {
        const int nxt_bs = (bs + 2 >= 3) ? bs - 1 : bs + 2;   // (bs+2)%3

        if (kt + 2 < TILES_PER_SPLIT) {
            cpasync_b(sb, B_OFF(nxt_bs), kt0 + kt + 2, tid);
            cp_commit();
        }
        if (kt + 1 < TILES_PER_SPLIT)
            sts_a(smem, A_OFF((kt + 1) & 1), arow, aq, aR);
        if (kt + 2 < TILES_PER_SPLIT)
            ldg_a(W, atrow, (kt0 + kt + 2) * K_TILE, aq, trow_ok, aR);

        compute_tile(sb, A_OFF(kt & 1), B_OFF(bs), wm, wn, lid, acc);

        if (kt + 2 < TILES_PER_SPLIT)      cp_wait<1>();   // B(kt+1) done
        else if (kt + 1 < TILES_PER_SPLIT) cp_wait<0>();
        __syncthreads();

        bs = (bs + 1 >= 3) ? 0 : bs + 1;
    }

    // ---- epilogue ----
    float* vp = g_vp + (size_t)split * BATCH * T_PAD;
    #pragma unroll
    for (int mt = 0; mt < 2; mt++) {
        #pragma unroll
        for (int nt = 0; nt < 2; nt++) {
            int r  = t0 + wm * 32 + mt * 16 + g;
            int cb = wn * 16 + nt * 8 + 2 * t4;
            vp[(size_t)cb       * T_PAD + r]     = acc[mt][nt][0];
            vp[(size_t)(cb + 1) * T_PAD + r]     = acc[mt][nt][1];
            vp[(size_t)cb       * T_PAD + r + 8] = acc[mt][nt][2];
            vp[(size_t)(cb + 1) * T_PAD + r + 8] = acc[mt][nt][3];
        }
    }
}

// ---------------------------------------------------------------------------
// Kernel 3: symmetric triu scatter + split-K reduce + bias
// ---------------------------------------------------------------------------
__global__ void scatter_kernel(float* __restrict__ out,
                               const float* __restrict__ bias) {
    int idx = blockIdx.x * blockDim.x + threadIdx.x;
    if (idx >= BATCH * NDIM * NDIM) return;
    int b = idx >> 14;
    int r = (idx >> 7) & 127;
    int c = idx & 127;
    int i = min(r, c);
    int j = max(r, c);
    int t = i * NDIM - (i * (i - 1)) / 2 + (j - i);
    out[idx] = g_vp[(size_t)b * T_PAD + t] +
               g_vp[(size_t)(BATCH + b) * T_PAD + t] + bias[t];
}

// ---------------------------------------------------------------------------
extern "C" void kernel_launch(void* const* d_in, const int* in_sizes, int n_in,
                              void* d_out, int out_size) {
    const float* x       = (const float*)d_in[0];
    const float* conv1_w = (const float*)d_in[1];
    const float* conv1_b = (const float*)d_in[2];
    const float* conv2_w = (const float*)d_in[3];
    const float* conv2_b = (const float*)d_in[4];
    const float* out_w   = (const float*)d_in[5];
    const float* out_b   = (const float*)d_in[6];
    float* out = (float*)d_out;

    cudaFuncSetAttribute(gemm_tc_kernel,
                         cudaFuncAttributeMaxDynamicSharedMemorySize, SMEM_BYTES);

    {
        int total = BATCH * LIN_PAD;
        conv_fuse_kernel<<<(total + 255) / 256, 256>>>(x, conv1_w, conv1_b,
                                                       conv2_w, conv2_b);
    }
    gemm_tc_kernel<<<N_MTILES * KSPLIT, 512, SMEM_BYTES>>>(out_w);
    {
        int total = BATCH * NDIM * NDIM;
        scatter_kernel<<<(total + 255) / 256, 256>>>(out, out_b);
    }
}